// round 2
// baseline (speedup 1.0000x reference)
#include <cuda_runtime.h>
#include <cstdint>

#define HID 64
#define MAX_NODES 100000

// Scratch (persistent across graph replays -> must be re-initialized each launch)
__device__ float g_m[(size_t)MAX_NODES * HID];    // relu(x @ W^T + b)
__device__ float g_agg[(size_t)MAX_NODES * HID];  // segment-sum accumulator

// ---------------------------------------------------------------------------
// K1: m = relu(x @ W^T + b), and zero g_agg.
// Block: 256 threads = 16 nodes x 16 quads (4 cols each).
// ---------------------------------------------------------------------------
__global__ __launch_bounds__(256) void k1_gemm_relu(
    const float* __restrict__ x, const float* __restrict__ W,
    const float* __restrict__ b, float* __restrict__ m,
    float* __restrict__ agg, int n_nodes)
{
    __shared__ float WT[HID * HID];   // WT[d*64 + k] = W[k*64 + d]
    __shared__ float xs[16 * HID];
    __shared__ float bs[HID];

    const int tid = threadIdx.x;

    #pragma unroll
    for (int i = tid; i < HID * HID; i += 256) {
        int k = i >> 6, d = i & 63;
        WT[d * HID + k] = W[i];
    }
    if (tid < HID) bs[tid] = b[tid];

    const int node0 = blockIdx.x * 16;
    #pragma unroll
    for (int i = tid; i < 16 * HID; i += 256) {
        int n = node0 + (i >> 6);
        xs[i] = (n < n_nodes) ? x[(size_t)n * HID + (i & 63)] : 0.0f;
    }
    __syncthreads();

    const int local = tid >> 4;   // node within tile
    const int q     = tid & 15;   // column quad
    const int n     = node0 + local;
    if (n >= n_nodes) return;

    const float* xrow = xs + local * HID;
    float4 acc = make_float4(0.f, 0.f, 0.f, 0.f);
    #pragma unroll
    for (int d = 0; d < HID; d++) {
        float xv = xrow[d];
        float4 w = *reinterpret_cast<const float4*>(&WT[d * HID + q * 4]);
        acc.x = fmaf(xv, w.x, acc.x);
        acc.y = fmaf(xv, w.y, acc.y);
        acc.z = fmaf(xv, w.z, acc.z);
        acc.w = fmaf(xv, w.w, acc.w);
    }
    float4 bb = *reinterpret_cast<const float4*>(&bs[q * 4]);
    acc.x = fmaxf(acc.x + bb.x, 0.f);
    acc.y = fmaxf(acc.y + bb.y, 0.f);
    acc.z = fmaxf(acc.z + bb.z, 0.f);
    acc.w = fmaxf(acc.w + bb.w, 0.f);

    const size_t off = (size_t)n * HID + q * 4;
    *reinterpret_cast<float4*>(&m[off]) = acc;
    *reinterpret_cast<float4*>(&agg[off]) = make_float4(0.f, 0.f, 0.f, 0.f);
}

// ---------------------------------------------------------------------------
// K2: agg[dst] += m[src] over edges. Thread = (edge, quad of 4 cols).
// Uses red.global.add.v4.f32 (no return) to quarter the atomic-op count.
// ---------------------------------------------------------------------------
__global__ __launch_bounds__(256) void k2_scatter(
    const int* __restrict__ edges, const float* __restrict__ m,
    float* __restrict__ agg, int n_edges)
{
    long long t = (long long)blockIdx.x * blockDim.x + threadIdx.x;
    int e = (int)(t >> 4);
    if (e >= n_edges) return;
    int q = (int)(t & 15);

    int dst = edges[e];             // edges[0][e]
    int src = edges[n_edges + e];   // edges[1][e]

    float4 v = *reinterpret_cast<const float4*>(&m[(size_t)src * HID + q * 4]);
    if (v.x == 0.f && v.y == 0.f && v.z == 0.f && v.w == 0.f) return;  // ReLU zeros

    float* p = &agg[(size_t)dst * HID + q * 4];
    asm volatile("red.global.add.v4.f32 [%0], {%1, %2, %3, %4};"
                 :: "l"(p), "f"(v.x), "f"(v.y), "f"(v.z), "f"(v.w)
                 : "memory");
}

// ---------------------------------------------------------------------------
// K3: out = norm_weight * ((x + agg) * rsqrt(mean((x+agg)^2) + eps)) + norm_bias
// Warp per node, float2 per lane, shfl reduction.
// ---------------------------------------------------------------------------
__global__ __launch_bounds__(256) void k3_rmsnorm(
    const float* __restrict__ x, const float* __restrict__ agg,
    const float* __restrict__ nw, const float* __restrict__ nb,
    float* __restrict__ out, int n_nodes)
{
    int warp = (int)(((long long)blockIdx.x * blockDim.x + threadIdx.x) >> 5);
    int lane = threadIdx.x & 31;
    if (warp >= n_nodes) return;

    size_t base = (size_t)warp * HID + lane * 2;
    float2 xv = *reinterpret_cast<const float2*>(&x[base]);
    float2 av = *reinterpret_cast<const float2*>(&agg[base]);
    float hx = xv.x + av.x;
    float hy = xv.y + av.y;

    float s = hx * hx + hy * hy;
    #pragma unroll
    for (int o = 16; o; o >>= 1) s += __shfl_xor_sync(0xFFFFFFFFu, s, o);

    float inv = rsqrtf(s * (1.0f / 64.0f) + 1e-5f);

    float2 w  = *reinterpret_cast<const float2*>(&nw[lane * 2]);
    float2 bb = *reinterpret_cast<const float2*>(&nb[lane * 2]);
    float2 o2;
    o2.x = fmaf(w.x, hx * inv, bb.x);
    o2.y = fmaf(w.y, hy * inv, bb.y);
    *reinterpret_cast<float2*>(&out[base]) = o2;
}

// ---------------------------------------------------------------------------
extern "C" void kernel_launch(void* const* d_in, const int* in_sizes, int n_in,
                              void* d_out, int out_size)
{
    const float* x  = (const float*)d_in[0];
    const int*   ed = (const int*)  d_in[1];
    const float* W  = (const float*)d_in[2];
    const float* b  = (const float*)d_in[3];
    const float* nw = (const float*)d_in[4];
    const float* nb = (const float*)d_in[5];
    float* out = (float*)d_out;

    const int n_nodes = in_sizes[0] / HID;
    const int n_edges = in_sizes[1] / 2;

    float* m_buf;
    float* agg_buf;
    cudaGetSymbolAddress((void**)&m_buf,   g_m);
    cudaGetSymbolAddress((void**)&agg_buf, g_agg);

    // K1: GEMM+ReLU + zero agg
    {
        int blocks = (n_nodes + 15) / 16;
        k1_gemm_relu<<<blocks, 256>>>(x, W, b, m_buf, agg_buf, n_nodes);
    }
    // K2: edge scatter via vector red
    {
        long long threads = (long long)n_edges * 16;
        int blocks = (int)((threads + 255) / 256);
        k2_scatter<<<blocks, 256>>>(ed, m_buf, agg_buf, n_edges);
    }
    // K3: residual + RMSNorm
    {
        long long threads = (long long)n_nodes * 32;
        int blocks = (int)((threads + 255) / 256);
        k3_rmsnorm<<<blocks, 256>>>(x, agg_buf, nw, nb, out, n_nodes);
    }
}

// round 5
// speedup vs baseline: 1.5634x; 1.5634x over previous
#include <cuda_runtime.h>
#include <cstdint>

#define HID 64
#define MAX_NODES 100000

// Scratch (persistent across graph replays -> re-initialized each launch)
__device__ float g_m[(size_t)MAX_NODES * HID];    // relu(x @ W^T + b)
__device__ float g_agg[(size_t)MAX_NODES * HID];  // segment-sum accumulator

// ---------------------------------------------------------------------------
// K1: m = relu(x @ W^T + b), and zero g_agg (coalesced).
// 128 threads/block = 4 warps; each lane computes ONE node row, all 64 output
// columns in 16 float4 register accumulators. W column broadcast from smem.
// ---------------------------------------------------------------------------
__global__ __launch_bounds__(128) void k1_gemm_relu(
    const float* __restrict__ x, const float* __restrict__ W,
    const float* __restrict__ b, float* __restrict__ m,
    float* __restrict__ agg, int n_nodes)
{
    __shared__ float WT[HID * HID];   // WT[d*64 + k] = W[k*64 + d]

    const int tid = threadIdx.x;
    const int node0 = blockIdx.x * 128;

    // Transpose W into smem (coalesced global reads)
    #pragma unroll
    for (int i = tid; i < HID * HID; i += 128) {
        int k = i >> 6, d = i & 63;
        WT[d * HID + k] = W[i];
    }

    // Zero agg tile (coalesced)
    {
        size_t lim = (size_t)n_nodes * HID;
        size_t base = (size_t)node0 * HID;
        #pragma unroll
        for (int i = tid; i < 128 * HID; i += 128) {
            size_t idx = base + i;
            if (idx < lim) agg[idx] = 0.0f;
        }
    }
    __syncthreads();

    const int node = node0 + tid;
    if (node >= n_nodes) return;

    const float4* __restrict__ WT4 = reinterpret_cast<const float4*>(WT);
    const float4* __restrict__ x4p =
        reinterpret_cast<const float4*>(x + (size_t)node * HID);
    const float4* __restrict__ b4 = reinterpret_cast<const float4*>(b);

    float4 acc[16];
    #pragma unroll
    for (int j = 0; j < 16; j++) acc[j] = __ldg(&b4[j]);

    #pragma unroll 1
    for (int dc = 0; dc < 16; dc++) {
        float4 xv4 = __ldg(&x4p[dc]);
        float xv[4] = {xv4.x, xv4.y, xv4.z, xv4.w};
        #pragma unroll
        for (int r = 0; r < 4; r++) {
            const int d = dc * 4 + r;
            const float xs = xv[r];
            #pragma unroll
            for (int j = 0; j < 16; j++) {
                float4 w = WT4[d * 16 + j];   // warp-broadcast LDS.128
                acc[j].x = fmaf(xs, w.x, acc[j].x);
                acc[j].y = fmaf(xs, w.y, acc[j].y);
                acc[j].z = fmaf(xs, w.z, acc[j].z);
                acc[j].w = fmaf(xs, w.w, acc[j].w);
            }
        }
    }

    float4* __restrict__ mrow = reinterpret_cast<float4*>(m + (size_t)node * HID);
    #pragma unroll
    for (int j = 0; j < 16; j++) {
        float4 v = acc[j];
        v.x = fmaxf(v.x, 0.f);
        v.y = fmaxf(v.y, 0.f);
        v.z = fmaxf(v.z, 0.f);
        v.w = fmaxf(v.w, 0.f);
        mrow[j] = v;
    }
}

// ---------------------------------------------------------------------------
// K2: agg[dst] += m[src] over edges. Thread = (edge, quad of 4 cols).
// red.global.add.v4.f32 (no return) quarters the atomic-op count.
// ---------------------------------------------------------------------------
__global__ __launch_bounds__(256) void k2_scatter(
    const int* __restrict__ edges, const float* __restrict__ m,
    float* __restrict__ agg, int n_edges)
{
    long long t = (long long)blockIdx.x * blockDim.x + threadIdx.x;
    int e = (int)(t >> 4);
    if (e >= n_edges) return;
    int q = (int)(t & 15);

    int dst = __ldg(&edges[e]);             // edges[0][e]
    int src = __ldg(&edges[n_edges + e]);   // edges[1][e]

    float4 v = *reinterpret_cast<const float4*>(&m[(size_t)src * HID + q * 4]);
    if (v.x == 0.f && v.y == 0.f && v.z == 0.f && v.w == 0.f) return;  // ReLU zeros

    float* p = &agg[(size_t)dst * HID + q * 4];
    asm volatile("red.global.add.v4.f32 [%0], {%1, %2, %3, %4};"
                 :: "l"(p), "f"(v.x), "f"(v.y), "f"(v.z), "f"(v.w)
                 : "memory");
}

// ---------------------------------------------------------------------------
// K3: out = norm_weight * ((x + agg) * rsqrt(mean((x+agg)^2) + eps)) + norm_bias
// Warp per node, float2 per lane, shfl reduction.
// ---------------------------------------------------------------------------
__global__ __launch_bounds__(256) void k3_rmsnorm(
    const float* __restrict__ x, const float* __restrict__ agg,
    const float* __restrict__ nw, const float* __restrict__ nb,
    float* __restrict__ out, int n_nodes)
{
    int warp = (int)(((long long)blockIdx.x * blockDim.x + threadIdx.x) >> 5);
    int lane = threadIdx.x & 31;
    if (warp >= n_nodes) return;

    size_t base = (size_t)warp * HID + lane * 2;
    float2 xv = *reinterpret_cast<const float2*>(&x[base]);
    float2 av = *reinterpret_cast<const float2*>(&agg[base]);
    float hx = xv.x + av.x;
    float hy = xv.y + av.y;

    float s = hx * hx + hy * hy;
    #pragma unroll
    for (int o = 16; o; o >>= 1) s += __shfl_xor_sync(0xFFFFFFFFu, s, o);

    float inv = rsqrtf(s * (1.0f / 64.0f) + 1e-5f);

    float2 w  = *reinterpret_cast<const float2*>(&nw[lane * 2]);
    float2 bb = *reinterpret_cast<const float2*>(&nb[lane * 2]);
    float2 o2;
    o2.x = fmaf(w.x, hx * inv, bb.x);
    o2.y = fmaf(w.y, hy * inv, bb.y);
    *reinterpret_cast<float2*>(&out[base]) = o2;
}

// ---------------------------------------------------------------------------
extern "C" void kernel_launch(void* const* d_in, const int* in_sizes, int n_in,
                              void* d_out, int out_size)
{
    const float* x  = (const float*)d_in[0];
    const int*   ed = (const int*)  d_in[1];
    const float* W  = (const float*)d_in[2];
    const float* b  = (const float*)d_in[3];
    const float* nw = (const float*)d_in[4];
    const float* nb = (const float*)d_in[5];
    float* out = (float*)d_out;

    const int n_nodes = in_sizes[0] / HID;
    const int n_edges = in_sizes[1] / 2;

    float* m_buf;
    float* agg_buf;
    cudaGetSymbolAddress((void**)&m_buf,   g_m);
    cudaGetSymbolAddress((void**)&agg_buf, g_agg);

    // K1: GEMM+ReLU + zero agg
    {
        int blocks = (n_nodes + 127) / 128;
        k1_gemm_relu<<<blocks, 128>>>(x, W, b, m_buf, agg_buf, n_nodes);
    }
    // K2: edge scatter via vector red
    {
        long long threads = (long long)n_edges * 16;
        int blocks = (int)((threads + 255) / 256);
        k2_scatter<<<blocks, 256>>>(ed, m_buf, agg_buf, n_edges);
    }
    // K3: residual + RMSNorm
    {
        long long threads = (long long)n_nodes * 32;
        int blocks = (int)((threads + 255) / 256);
        k3_rmsnorm<<<blocks, 256>>>(x, agg_buf, nw, nb, out, n_nodes);
    }
}